// round 2
// baseline (speedup 1.0000x reference)
#include <cuda_runtime.h>
#include <math.h>
#include <stdint.h>

// ---------------- problem constants ----------------
#define DIM      3072
#define NHEADS   24
#define HD       128
#define S_TXT    512
#define S_IMG    2048
#define S_TOT    2560          // S_TXT + S_IMG
#define SOFTMAX_SCALE 0.08838834764831845f   // 1/sqrt(128)

// ---------------- scratch (static device arrays; no cudaMalloc allowed) ------
__device__ float g_Q[S_TOT * DIM];
__device__ float g_K[S_TOT * DIM];
__device__ float g_V[S_TOT * DIM];
__device__ float g_O[S_TOT * DIM];
__device__ float g_S[(size_t)NHEADS * S_TOT * S_TOT];   // 24*2560*2560 fp32 ~ 630 MB

// ---------------- GEMM 1: big NN GEMM with row-split sources -----------------
// C = A @ W + b, M = 2560, N = K = 3072.
// Rows [0,512): A0/W0/b0 -> C0 ; rows [512,2560): A1/W1/b1 -> C1 (shifted).
// Tiles: BM=BN=128, BK=8, 256 threads, 8x8 per thread, register-prefetch
// double buffering on the global loads.
__global__ __launch_bounds__(256) void gemm_big(
    const float* __restrict__ A0, const float* __restrict__ A1,
    const float* __restrict__ W0, const float* __restrict__ W1,
    const float* __restrict__ b0, const float* __restrict__ b1,
    float* __restrict__ C0, float* __restrict__ C1)
{
    const int bm = blockIdx.y * 128;
    const int bn = blockIdx.x * 128;

    const float* A; const float* W; const float* bias; float* C; int rowoff;
    if (bm < S_TXT) { A = A0; W = W0; bias = b0; C = C0; rowoff = bm; }
    else            { A = A1; W = W1; bias = b1; C = C1; rowoff = bm - S_TXT; }

    __shared__ float As[8][128];
    __shared__ float Bs[8][128];

    const int tid = threadIdx.x;
    const int tx = tid & 15;
    const int ty = tid >> 4;

    const int ar = tid >> 1, ac = (tid & 1) * 4;   // A tile loader: 128 rows x 8 k
    const int br = tid >> 5, bc = (tid & 31) * 4;  // W tile loader: 8 k x 128 cols

    const float* Aptr = A + (size_t)(rowoff + ar) * DIM + ac;
    const float* Wptr = W + (size_t)br * DIM + bn + bc;

    float acc[8][8];
    #pragma unroll
    for (int i = 0; i < 8; i++)
        #pragma unroll
        for (int j = 0; j < 8; j++) acc[i][j] = 0.f;

    // prefetch first tile into registers
    float4 av = *(const float4*)(Aptr);
    float4 wv = *(const float4*)(Wptr);

    for (int k0 = 0; k0 < DIM; k0 += 8) {
        As[ac + 0][ar] = av.x; As[ac + 1][ar] = av.y;
        As[ac + 2][ar] = av.z; As[ac + 3][ar] = av.w;
        *(float4*)&Bs[br][bc] = wv;
        __syncthreads();

        // issue next tile's loads before the FFMA block (latency overlap)
        if (k0 + 8 < DIM) {
            av = *(const float4*)(Aptr + k0 + 8);
            wv = *(const float4*)(Wptr + (size_t)(k0 + 8) * DIM);
        }

        #pragma unroll
        for (int k = 0; k < 8; ++k) {
            float4 a0 = *(const float4*)&As[k][ty * 8];
            float4 a1 = *(const float4*)&As[k][ty * 8 + 4];
            float4 v0 = *(const float4*)&Bs[k][tx * 8];
            float4 v1 = *(const float4*)&Bs[k][tx * 8 + 4];
            float avr[8] = {a0.x, a0.y, a0.z, a0.w, a1.x, a1.y, a1.z, a1.w};
            float bvr[8] = {v0.x, v0.y, v0.z, v0.w, v1.x, v1.y, v1.z, v1.w};
            #pragma unroll
            for (int i = 0; i < 8; i++)
                #pragma unroll
                for (int j = 0; j < 8; j++) acc[i][j] += avr[i] * bvr[j];
        }
        __syncthreads();
    }

    float bb[8];
    #pragma unroll
    for (int j = 0; j < 8; j++) bb[j] = bias[bn + tx * 8 + j];

    #pragma unroll
    for (int i = 0; i < 8; i++) {
        float* Crow = C + (size_t)(rowoff + ty * 8 + i) * DIM + bn + tx * 8;
        float4 o0, o1;
        o0.x = acc[i][0] + bb[0]; o0.y = acc[i][1] + bb[1];
        o0.z = acc[i][2] + bb[2]; o0.w = acc[i][3] + bb[3];
        o1.x = acc[i][4] + bb[4]; o1.y = acc[i][5] + bb[5];
        o1.z = acc[i][6] + bb[6]; o1.w = acc[i][7] + bb[7];
        *(float4*)Crow = o0;
        *(float4*)(Crow + 4) = o1;
    }
}

// ---------------- GEMM 2: per-head scores, S = Q @ K^T (NT) -------------------
// S[h][m][n] = sum_d Q[m][h*128+d] * K[n][h*128+d];  M = N = 2560, Kdim = 128.
__global__ __launch_bounds__(256) void gemm_scores(
    const float* __restrict__ Q, const float* __restrict__ K, float* __restrict__ S)
{
    const int h  = blockIdx.z;
    const int bm = blockIdx.y * 128;
    const int bn = blockIdx.x * 128;
    const float* A = Q + h * HD;
    const float* B = K + h * HD;

    __shared__ float As[8][128];
    __shared__ float Bs[8][128];

    const int tid = threadIdx.x;
    const int tx = tid & 15, ty = tid >> 4;
    const int ar = tid >> 1, ac = (tid & 1) * 4;

    const float* Aptr = A + (size_t)(bm + ar) * DIM + ac;
    const float* Bptr = B + (size_t)(bn + ar) * DIM + ac;

    float acc[8][8];
    #pragma unroll
    for (int i = 0; i < 8; i++)
        #pragma unroll
        for (int j = 0; j < 8; j++) acc[i][j] = 0.f;

    float4 av = *(const float4*)(Aptr);
    float4 bv = *(const float4*)(Bptr);

    for (int k0 = 0; k0 < HD; k0 += 8) {
        As[ac + 0][ar] = av.x; As[ac + 1][ar] = av.y;
        As[ac + 2][ar] = av.z; As[ac + 3][ar] = av.w;
        Bs[ac + 0][ar] = bv.x; Bs[ac + 1][ar] = bv.y;
        Bs[ac + 2][ar] = bv.z; Bs[ac + 3][ar] = bv.w;
        __syncthreads();

        if (k0 + 8 < HD) {
            av = *(const float4*)(Aptr + k0 + 8);
            bv = *(const float4*)(Bptr + k0 + 8);
        }

        #pragma unroll
        for (int k = 0; k < 8; ++k) {
            float4 a0 = *(const float4*)&As[k][ty * 8];
            float4 a1 = *(const float4*)&As[k][ty * 8 + 4];
            float4 v0 = *(const float4*)&Bs[k][tx * 8];
            float4 v1 = *(const float4*)&Bs[k][tx * 8 + 4];
            float avr[8] = {a0.x, a0.y, a0.z, a0.w, a1.x, a1.y, a1.z, a1.w};
            float bvr[8] = {v0.x, v0.y, v0.z, v0.w, v1.x, v1.y, v1.z, v1.w};
            #pragma unroll
            for (int i = 0; i < 8; i++)
                #pragma unroll
                for (int j = 0; j < 8; j++) acc[i][j] += avr[i] * bvr[j];
        }
        __syncthreads();
    }

    float* Sh = S + (size_t)h * S_TOT * S_TOT;
    #pragma unroll
    for (int i = 0; i < 8; i++) {
        float* Crow = Sh + (size_t)(bm + ty * 8 + i) * S_TOT + bn + tx * 8;
        *(float4*)Crow       = make_float4(acc[i][0], acc[i][1], acc[i][2], acc[i][3]);
        *(float4*)(Crow + 4) = make_float4(acc[i][4], acc[i][5], acc[i][6], acc[i][7]);
    }
}

// ---------------- softmax over rows of length 2560 (scale folded in) ----------
__global__ __launch_bounds__(256) void softmax_kernel(float* __restrict__ S)
{
    float* row = S + (size_t)blockIdx.x * S_TOT;
    const int tid = threadIdx.x;
    __shared__ float red[8];

    float v[10];
    float m = -1e30f;
    #pragma unroll
    for (int i = 0; i < 10; i++) { v[i] = row[tid + i * 256]; m = fmaxf(m, v[i]); }
    #pragma unroll
    for (int o = 16; o; o >>= 1) m = fmaxf(m, __shfl_xor_sync(0xffffffffu, m, o));
    const int wid = tid >> 5, lane = tid & 31;
    if (lane == 0) red[wid] = m;
    __syncthreads();
    float mm = red[0];
    #pragma unroll
    for (int i = 1; i < 8; i++) mm = fmaxf(mm, red[i]);
    __syncthreads();

    float sum = 0.f;
    #pragma unroll
    for (int i = 0; i < 10; i++) {
        v[i] = __expf((v[i] - mm) * SOFTMAX_SCALE);
        sum += v[i];
    }
    #pragma unroll
    for (int o = 16; o; o >>= 1) sum += __shfl_xor_sync(0xffffffffu, sum, o);
    if (lane == 0) red[wid] = sum;
    __syncthreads();
    float tot = red[0];
    #pragma unroll
    for (int i = 1; i < 8; i++) tot += red[i];
    const float inv = 1.f / tot;
    #pragma unroll
    for (int i = 0; i < 10; i++) row[tid + i * 256] = v[i] * inv;
}

// ---------------- GEMM 3: per-head PV, O = P @ V (NN) -------------------------
// M = 2560, N = 128 (one block-col), Kdim = 2560.
__global__ __launch_bounds__(256) void gemm_pv(
    const float* __restrict__ S, const float* __restrict__ V, float* __restrict__ O)
{
    const int h  = blockIdx.z;
    const int bm = blockIdx.y * 128;
    const float* A = S + (size_t)h * S_TOT * S_TOT;
    const float* B = V + h * HD;

    __shared__ float As[8][128];
    __shared__ float Bs[8][128];

    const int tid = threadIdx.x;
    const int tx = tid & 15, ty = tid >> 4;
    const int ar = tid >> 1, ac = (tid & 1) * 4;
    const int br = tid >> 5, bc = (tid & 31) * 4;

    const float* Aptr = A + (size_t)(bm + ar) * S_TOT + ac;
    const float* Bptr = B + (size_t)br * DIM + bc;

    float acc[8][8];
    #pragma unroll
    for (int i = 0; i < 8; i++)
        #pragma unroll
        for (int j = 0; j < 8; j++) acc[i][j] = 0.f;

    float4 av = *(const float4*)(Aptr);
    float4 bv = *(const float4*)(Bptr);

    for (int k0 = 0; k0 < S_TOT; k0 += 8) {
        As[ac + 0][ar] = av.x; As[ac + 1][ar] = av.y;
        As[ac + 2][ar] = av.z; As[ac + 3][ar] = av.w;
        *(float4*)&Bs[br][bc] = bv;
        __syncthreads();

        if (k0 + 8 < S_TOT) {
            av = *(const float4*)(Aptr + k0 + 8);
            bv = *(const float4*)(Bptr + (size_t)(k0 + 8) * DIM);
        }

        #pragma unroll
        for (int k = 0; k < 8; ++k) {
            float4 a0 = *(const float4*)&As[k][ty * 8];
            float4 a1 = *(const float4*)&As[k][ty * 8 + 4];
            float4 v0 = *(const float4*)&Bs[k][tx * 8];
            float4 v1 = *(const float4*)&Bs[k][tx * 8 + 4];
            float avr[8] = {a0.x, a0.y, a0.z, a0.w, a1.x, a1.y, a1.z, a1.w};
            float bvr[8] = {v0.x, v0.y, v0.z, v0.w, v1.x, v1.y, v1.z, v1.w};
            #pragma unroll
            for (int i = 0; i < 8; i++)
                #pragma unroll
                for (int j = 0; j < 8; j++) acc[i][j] += avr[i] * bvr[j];
        }
        __syncthreads();
    }

    #pragma unroll
    for (int i = 0; i < 8; i++) {
        float* Crow = O + (size_t)(bm + ty * 8 + i) * DIM + h * HD + tx * 8;
        *(float4*)Crow       = make_float4(acc[i][0], acc[i][1], acc[i][2], acc[i][3]);
        *(float4*)(Crow + 4) = make_float4(acc[i][4], acc[i][5], acc[i][6], acc[i][7]);
    }
}

// ---------------- RMS-norm + RoPE on Q and K (warp per (token, head)) ---------
__global__ __launch_bounds__(256) void norm_rope_kernel(
    float* __restrict__ Q, float* __restrict__ K,
    const float* __restrict__ csn, const float* __restrict__ snn,
    const float* __restrict__ g_q, const float* __restrict__ g_aq,
    const float* __restrict__ g_k, const float* __restrict__ g_ak)
{
    const int warp = (blockIdx.x * blockDim.x + threadIdx.x) >> 5;
    const int lane = threadIdx.x & 31;
    if (warp >= S_TOT * NHEADS) return;
    const int s = warp / NHEADS;
    const int h = warp % NHEADS;

    float* X;
    const float* g;
    if (blockIdx.y == 0) { X = Q; g = (s < S_TXT) ? g_aq : g_q; }
    else                 { X = K; g = (s < S_TXT) ? g_ak : g_k; }

    float* row = X + (size_t)s * DIM + h * HD;
    const int d = lane * 4;
    float4 x = *(float4*)(row + d);

    float ss = x.x * x.x + x.y * x.y + x.z * x.z + x.w * x.w;
    #pragma unroll
    for (int o = 16; o; o >>= 1) ss += __shfl_xor_sync(0xffffffffu, ss, o);
    const float r = rsqrtf(ss * (1.f / (float)HD) + 1e-6f);

    float4 gv = *(const float4*)(g + d);
    x.x *= r * gv.x; x.y *= r * gv.y; x.z *= r * gv.z; x.w *= r * gv.w;

    float4 c  = *(const float4*)(csn + (size_t)s * HD + d);
    float4 sn = *(const float4*)(snn + (size_t)s * HD + d);
    float4 o;
    o.x = x.x * c.x - x.y * sn.x;
    o.y = x.y * c.y + x.x * sn.y;
    o.z = x.z * c.z - x.w * sn.z;
    o.w = x.w * c.w + x.z * sn.w;
    *(float4*)(row + d) = o;
}

// ---------------- launch ------------------------------------------------------
extern "C" void kernel_launch(void* const* d_in, const int* in_sizes, int n_in,
                              void* d_out, int out_size)
{
    const float** in = (const float**)d_in;
    const float *hid = in[0], *enc = in[1], *cosr = in[2], *sinr = in[3];
    const float *Wq, *bq, *Wk, *bk, *Wv, *bv, *Waq, *baq, *Wak, *bak, *Wav, *bav;
    const float *gq, *gk, *gaq, *gak, *Wout, *bout, *Wadd, *badd;

    if (in_sizes[5] == DIM) {
        // reference-signature order
        Wq = in[4];  bq = in[5];  Wk = in[6];  bk = in[7];  Wv = in[8];  bv = in[9];
        Waq = in[10]; baq = in[11]; Wak = in[12]; bak = in[13]; Wav = in[14]; bav = in[15];
        gq = in[16]; gk = in[17]; gaq = in[18]; gak = in[19];
        Wout = in[20]; bout = in[21]; Wadd = in[22]; badd = in[23];
    } else {
        // setup_inputs dict order
        Wq = in[4]; Wk = in[5]; Wv = in[6]; Waq = in[7]; Wak = in[8]; Wav = in[9];
        Wout = in[10]; Wadd = in[11];
        bq = in[12]; bk = in[13]; bv = in[14]; baq = in[15]; bak = in[16]; bav = in[17];
        bout = in[18]; badd = in[19];
        gq = in[20]; gk = in[21]; gaq = in[22]; gak = in[23];
    }

    float *Qb, *Kb, *Vb, *Ob, *Sb;
    cudaGetSymbolAddress((void**)&Qb, g_Q);
    cudaGetSymbolAddress((void**)&Kb, g_K);
    cudaGetSymbolAddress((void**)&Vb, g_V);
    cudaGetSymbolAddress((void**)&Ob, g_O);
    cudaGetSymbolAddress((void**)&Sb, g_S);

    float* out = (float*)d_out;
    float* img_out = out;                          // [2048, 3072]
    float* enc_out = out + (size_t)S_IMG * DIM;    // [512, 3072]

    dim3 gBig(DIM / 128, S_TOT / 128);             // (24, 20)

    // 1-3. QKV projections (txt rows use Wa*, img rows use W*)
    gemm_big<<<gBig, 256>>>(enc, hid, Waq, Wq, baq, bq, Qb, Qb + (size_t)S_TXT * DIM);
    gemm_big<<<gBig, 256>>>(enc, hid, Wak, Wk, bak, bk, Kb, Kb + (size_t)S_TXT * DIM);
    gemm_big<<<gBig, 256>>>(enc, hid, Wav, Wv, bav, bv, Vb, Vb + (size_t)S_TXT * DIM);

    // 4. RMS-norm + RoPE on Q and K
    dim3 gNR((S_TOT * NHEADS * 32) / 256, 2);      // (7680, 2)
    norm_rope_kernel<<<gNR, 256>>>(Qb, Kb, cosr, sinr, gq, gaq, gk, gak);

    // 5. Scores S = Q K^T per head
    dim3 gSc(S_TOT / 128, S_TOT / 128, NHEADS);    // (20, 20, 24)
    gemm_scores<<<gSc, 256>>>(Qb, Kb, Sb);

    // 6. Softmax (scale folded in)
    softmax_kernel<<<NHEADS * S_TOT, 256>>>(Sb);

    // 7. O = P V per head
    dim3 gPV(1, S_TOT / 128, NHEADS);              // (1, 20, 24)
    gemm_pv<<<gPV, 256>>>(Sb, Vb, Ob);

    // 8. Output projections: txt rows -> Wadd -> enc_out; img rows -> Wout -> img_out
    gemm_big<<<gBig, 256>>>(Ob, Ob + (size_t)S_TXT * DIM, Wadd, Wout, badd, bout,
                            enc_out, img_out);
}

// round 3
// speedup vs baseline: 2.1466x; 2.1466x over previous
#include <cuda_runtime.h>
#include <math.h>
#include <stdint.h>

// ---------------- problem constants ----------------
#define DIM      3072
#define NHEADS   24
#define HD       128
#define S_TXT    512
#define S_IMG    2048
#define S_TOT    2560          // S_TXT + S_IMG
#define SOFTMAX_SCALE 0.08838834764831845f   // 1/sqrt(128)

#define PAD_A 36     // 128x32 tile, row pitch 36 (bank: 4g+tig, conflict-free frags)
#define PAD_B 136    // 32x128 tile, row pitch 136 (bank: 8*tig+g, conflict-free frags)

// ---------------- scratch (static device arrays; no cudaMalloc allowed) ------
__device__ float g_Q[S_TOT * DIM];
__device__ float g_K[S_TOT * DIM];
__device__ float g_V[S_TOT * DIM];
__device__ float g_O[S_TOT * DIM];
__device__ float g_S[(size_t)NHEADS * S_TOT * S_TOT];   // ~630 MB fp32

// ---------------- tf32 helpers ------------------------------------------------
__device__ __forceinline__ uint32_t f2tf32(float f) {
    uint32_t u;
    asm("cvt.rna.tf32.f32 %0, %1;" : "=r"(u) : "f"(f));
    return u;
}

__device__ __forceinline__ void mma_tf32(float c[4],
    uint32_t a0, uint32_t a1, uint32_t a2, uint32_t a3,
    uint32_t b0, uint32_t b1)
{
    asm volatile(
        "mma.sync.aligned.m16n8k8.row.col.f32.tf32.tf32.f32 "
        "{%0,%1,%2,%3},{%4,%5,%6,%7},{%8,%9},{%0,%1,%2,%3};"
        : "+f"(c[0]), "+f"(c[1]), "+f"(c[2]), "+f"(c[3])
        : "r"(a0), "r"(a1), "r"(a2), "r"(a3), "r"(b0), "r"(b1));
}

__device__ __forceinline__ uint4 cvt4(float4 v) {
    uint4 u;
    u.x = f2tf32(v.x); u.y = f2tf32(v.y); u.z = f2tf32(v.z); u.w = f2tf32(v.w);
    return u;
}

// ---------------- GEMM 1: big NN GEMM (tf32 MMA), row-split sources -----------
// C = A @ W + b, M = 2560, N = K = 3072. BM=BN=128, BK=32, 256 thr,
// 8 warps as 2(M)x4(N), warp tile 64x32, m16n8k8 tf32.
__global__ __launch_bounds__(256) void gemm_big_mma(
    const float* __restrict__ A0, const float* __restrict__ A1,
    const float* __restrict__ W0, const float* __restrict__ W1,
    const float* __restrict__ bv0, const float* __restrict__ bv1,
    float* __restrict__ C0, float* __restrict__ C1)
{
    const int bm = blockIdx.y * 128;
    const int bn = blockIdx.x * 128;

    const float* A; const float* W; const float* bias; float* C; int rowoff;
    if (bm < S_TXT) { A = A0; W = W0; bias = bv0; C = C0; rowoff = bm; }
    else            { A = A1; W = W1; bias = bv1; C = C1; rowoff = bm - S_TXT; }

    __shared__ uint32_t As[128][PAD_A];
    __shared__ uint32_t Bs[32][PAD_B];

    const int tid  = threadIdx.x;
    const int warp = tid >> 5, lane = tid & 31;
    const int g = lane >> 2, tig = lane & 3;
    const int wm = warp >> 2, wn = warp & 3;

    const int arow = tid >> 1, acol = (tid & 1) * 16;   // A: 128 rows x 32 k
    const int brow = tid >> 3, bcol = (tid & 7) * 16;   // B: 32 k x 128 n

    const float* Ap = A + (size_t)(rowoff + arow) * DIM + acol;
    const float* Wp = W + (size_t)brow * DIM + bn + bcol;

    float c[4][4][4];
    #pragma unroll
    for (int mt = 0; mt < 4; mt++)
        #pragma unroll
        for (int nt = 0; nt < 4; nt++)
            #pragma unroll
            for (int i = 0; i < 4; i++) c[mt][nt][i] = 0.f;

    float4 pa[4], pb[4];
    #pragma unroll
    for (int i = 0; i < 4; i++) {
        pa[i] = *(const float4*)(Ap + 4 * i);
        pb[i] = *(const float4*)(Wp + 4 * i);
    }

    for (int k0 = 0; k0 < DIM; k0 += 32) {
        #pragma unroll
        for (int i = 0; i < 4; i++) {
            *(uint4*)&As[arow][acol + 4 * i] = cvt4(pa[i]);
            *(uint4*)&Bs[brow][bcol + 4 * i] = cvt4(pb[i]);
        }
        __syncthreads();

        if (k0 + 32 < DIM) {
            #pragma unroll
            for (int i = 0; i < 4; i++) {
                pa[i] = *(const float4*)(Ap + k0 + 32 + 4 * i);
                pb[i] = *(const float4*)(Wp + (size_t)(k0 + 32) * DIM + 4 * i);
            }
        }

        #pragma unroll
        for (int ks = 0; ks < 4; ks++) {
            uint32_t af[4][4], bf[4][2];
            #pragma unroll
            for (int mt = 0; mt < 4; mt++) {
                const int r0 = wm * 64 + mt * 16 + g;
                af[mt][0] = As[r0][ks * 8 + tig];
                af[mt][1] = As[r0 + 8][ks * 8 + tig];
                af[mt][2] = As[r0][ks * 8 + tig + 4];
                af[mt][3] = As[r0 + 8][ks * 8 + tig + 4];
            }
            #pragma unroll
            for (int nt = 0; nt < 4; nt++) {
                const int cn = wn * 32 + nt * 8 + g;
                bf[nt][0] = Bs[ks * 8 + tig][cn];
                bf[nt][1] = Bs[ks * 8 + tig + 4][cn];
            }
            #pragma unroll
            for (int mt = 0; mt < 4; mt++)
                #pragma unroll
                for (int nt = 0; nt < 4; nt++)
                    mma_tf32(c[mt][nt], af[mt][0], af[mt][1], af[mt][2], af[mt][3],
                             bf[nt][0], bf[nt][1]);
        }
        __syncthreads();
    }

    #pragma unroll
    for (int mt = 0; mt < 4; mt++) {
        const int r0 = rowoff + wm * 64 + mt * 16 + g;
        #pragma unroll
        for (int nt = 0; nt < 4; nt++) {
            const int cn = bn + wn * 32 + nt * 8 + tig * 2;
            const float bx = bias[cn], by = bias[cn + 1];
            float2 v0 = make_float2(c[mt][nt][0] + bx, c[mt][nt][1] + by);
            float2 v1 = make_float2(c[mt][nt][2] + bx, c[mt][nt][3] + by);
            *(float2*)(C + (size_t)r0 * DIM + cn)       = v0;
            *(float2*)(C + (size_t)(r0 + 8) * DIM + cn) = v1;
        }
    }
}

// ---------------- GEMM 2: scores S = Q @ K^T (tf32 MMA, NT) -------------------
// Both Q and K tiles stored row-major [row][d]; K tile read directly as the
// col-major B fragment (B(k,n) = K[n][k]).
__global__ __launch_bounds__(256) void gemm_scores_mma(
    const float* __restrict__ Q, const float* __restrict__ K, float* __restrict__ S)
{
    const int h  = blockIdx.z;
    const int bm = blockIdx.y * 128;
    const int bn = blockIdx.x * 128;
    const float* A = Q + h * HD;
    const float* B = K + h * HD;

    __shared__ uint32_t As[128][PAD_A];
    __shared__ uint32_t Bsn[128][PAD_A];

    const int tid  = threadIdx.x;
    const int warp = tid >> 5, lane = tid & 31;
    const int g = lane >> 2, tig = lane & 3;
    const int wm = warp >> 2, wn = warp & 3;

    const int arow = tid >> 1, acol = (tid & 1) * 16;

    const float* Ap = A + (size_t)(bm + arow) * DIM + acol;
    const float* Bp = B + (size_t)(bn + arow) * DIM + acol;

    float c[4][4][4];
    #pragma unroll
    for (int mt = 0; mt < 4; mt++)
        #pragma unroll
        for (int nt = 0; nt < 4; nt++)
            #pragma unroll
            for (int i = 0; i < 4; i++) c[mt][nt][i] = 0.f;

    float4 pa[4], pb[4];
    #pragma unroll
    for (int i = 0; i < 4; i++) {
        pa[i] = *(const float4*)(Ap + 4 * i);
        pb[i] = *(const float4*)(Bp + 4 * i);
    }

    for (int k0 = 0; k0 < HD; k0 += 32) {
        #pragma unroll
        for (int i = 0; i < 4; i++) {
            *(uint4*)&As[arow][acol + 4 * i]  = cvt4(pa[i]);
            *(uint4*)&Bsn[arow][acol + 4 * i] = cvt4(pb[i]);
        }
        __syncthreads();

        if (k0 + 32 < HD) {
            #pragma unroll
            for (int i = 0; i < 4; i++) {
                pa[i] = *(const float4*)(Ap + k0 + 32 + 4 * i);
                pb[i] = *(const float4*)(Bp + k0 + 32 + 4 * i);
            }
        }

        #pragma unroll
        for (int ks = 0; ks < 4; ks++) {
            uint32_t af[4][4], bf[4][2];
            #pragma unroll
            for (int mt = 0; mt < 4; mt++) {
                const int r0 = wm * 64 + mt * 16 + g;
                af[mt][0] = As[r0][ks * 8 + tig];
                af[mt][1] = As[r0 + 8][ks * 8 + tig];
                af[mt][2] = As[r0][ks * 8 + tig + 4];
                af[mt][3] = As[r0 + 8][ks * 8 + tig + 4];
            }
            #pragma unroll
            for (int nt = 0; nt < 4; nt++) {
                const int rn = wn * 32 + nt * 8 + g;
                bf[nt][0] = Bsn[rn][ks * 8 + tig];
                bf[nt][1] = Bsn[rn][ks * 8 + tig + 4];
            }
            #pragma unroll
            for (int mt = 0; mt < 4; mt++)
                #pragma unroll
                for (int nt = 0; nt < 4; nt++)
                    mma_tf32(c[mt][nt], af[mt][0], af[mt][1], af[mt][2], af[mt][3],
                             bf[nt][0], bf[nt][1]);
        }
        __syncthreads();
    }

    float* Sh = S + (size_t)h * S_TOT * S_TOT;
    #pragma unroll
    for (int mt = 0; mt < 4; mt++) {
        const int r0 = bm + wm * 64 + mt * 16 + g;
        #pragma unroll
        for (int nt = 0; nt < 4; nt++) {
            const int cn = bn + wn * 32 + nt * 8 + tig * 2;
            *(float2*)(Sh + (size_t)r0 * S_TOT + cn)       = make_float2(c[mt][nt][0], c[mt][nt][1]);
            *(float2*)(Sh + (size_t)(r0 + 8) * S_TOT + cn) = make_float2(c[mt][nt][2], c[mt][nt][3]);
        }
    }
}

// ---------------- softmax over rows of length 2560 (scale folded in) ----------
__global__ __launch_bounds__(128) void softmax_kernel(float* __restrict__ S)
{
    float4* row = (float4*)(S + (size_t)blockIdx.x * S_TOT);
    const int tid = threadIdx.x;
    __shared__ float red[4];

    float4 v[5];
    float m = -1e30f;
    #pragma unroll
    for (int i = 0; i < 5; i++) {
        v[i] = row[tid + i * 128];
        m = fmaxf(m, fmaxf(fmaxf(v[i].x, v[i].y), fmaxf(v[i].z, v[i].w)));
    }
    #pragma unroll
    for (int o = 16; o; o >>= 1) m = fmaxf(m, __shfl_xor_sync(0xffffffffu, m, o));
    const int wid = tid >> 5, lane = tid & 31;
    if (lane == 0) red[wid] = m;
    __syncthreads();
    float mm = fmaxf(fmaxf(red[0], red[1]), fmaxf(red[2], red[3]));
    __syncthreads();

    float sum = 0.f;
    #pragma unroll
    for (int i = 0; i < 5; i++) {
        v[i].x = __expf((v[i].x - mm) * SOFTMAX_SCALE);
        v[i].y = __expf((v[i].y - mm) * SOFTMAX_SCALE);
        v[i].z = __expf((v[i].z - mm) * SOFTMAX_SCALE);
        v[i].w = __expf((v[i].w - mm) * SOFTMAX_SCALE);
        sum += v[i].x + v[i].y + v[i].z + v[i].w;
    }
    #pragma unroll
    for (int o = 16; o; o >>= 1) sum += __shfl_xor_sync(0xffffffffu, sum, o);
    if (lane == 0) red[wid] = sum;
    __syncthreads();
    const float inv = 1.f / (red[0] + red[1] + red[2] + red[3]);
    #pragma unroll
    for (int i = 0; i < 5; i++) {
        v[i].x *= inv; v[i].y *= inv; v[i].z *= inv; v[i].w *= inv;
        row[tid + i * 128] = v[i];
    }
}

// ---------------- GEMM 3: per-head PV, O = P @ V (tf32 MMA, NN) ---------------
// M = 2560 (grid.x m-blocks), N = 128 = whole head, Kdim = 2560.
__global__ __launch_bounds__(256) void gemm_pv_mma(
    const float* __restrict__ S, const float* __restrict__ V, float* __restrict__ O)
{
    const int h  = blockIdx.y;
    const int bm = blockIdx.x * 128;
    const float* A = S + (size_t)h * S_TOT * S_TOT;
    const float* B = V + h * HD;

    __shared__ uint32_t As[128][PAD_A];
    __shared__ uint32_t Bs[32][PAD_B];

    const int tid  = threadIdx.x;
    const int warp = tid >> 5, lane = tid & 31;
    const int g = lane >> 2, tig = lane & 3;
    const int wm = warp >> 2, wn = warp & 3;

    const int arow = tid >> 1, acol = (tid & 1) * 16;
    const int brow = tid >> 3, bcol = (tid & 7) * 16;

    const float* Ap = A + (size_t)(bm + arow) * S_TOT + acol;
    const float* Bp = B + (size_t)brow * DIM + bcol;

    float c[4][4][4];
    #pragma unroll
    for (int mt = 0; mt < 4; mt++)
        #pragma unroll
        for (int nt = 0; nt < 4; nt++)
            #pragma unroll
            for (int i = 0; i < 4; i++) c[mt][nt][i] = 0.f;

    float4 pa[4], pb[4];
    #pragma unroll
    for (int i = 0; i < 4; i++) {
        pa[i] = *(const float4*)(Ap + 4 * i);
        pb[i] = *(const float4*)(Bp + 4 * i);
    }

    for (int k0 = 0; k0 < S_TOT; k0 += 32) {
        #pragma unroll
        for (int i = 0; i < 4; i++) {
            *(uint4*)&As[arow][acol + 4 * i] = cvt4(pa[i]);
            *(uint4*)&Bs[brow][bcol + 4 * i] = cvt4(pb[i]);
        }
        __syncthreads();

        if (k0 + 32 < S_TOT) {
            #pragma unroll
            for (int i = 0; i < 4; i++) {
                pa[i] = *(const float4*)(Ap + k0 + 32 + 4 * i);
                pb[i] = *(const float4*)(Bp + (size_t)(k0 + 32) * DIM + 4 * i);
            }
        }

        #pragma unroll
        for (int ks = 0; ks < 4; ks++) {
            uint32_t af[4][4], bf[4][2];
            #pragma unroll
            for (int mt = 0; mt < 4; mt++) {
                const int r0 = wm * 64 + mt * 16 + g;
                af[mt][0] = As[r0][ks * 8 + tig];
                af[mt][1] = As[r0 + 8][ks * 8 + tig];
                af[mt][2] = As[r0][ks * 8 + tig + 4];
                af[mt][3] = As[r0 + 8][ks * 8 + tig + 4];
            }
            #pragma unroll
            for (int nt = 0; nt < 4; nt++) {
                const int cn = wn * 32 + nt * 8 + g;
                bf[nt][0] = Bs[ks * 8 + tig][cn];
                bf[nt][1] = Bs[ks * 8 + tig + 4][cn];
            }
            #pragma unroll
            for (int mt = 0; mt < 4; mt++)
                #pragma unroll
                for (int nt = 0; nt < 4; nt++)
                    mma_tf32(c[mt][nt], af[mt][0], af[mt][1], af[mt][2], af[mt][3],
                             bf[nt][0], bf[nt][1]);
        }
        __syncthreads();
    }

    #pragma unroll
    for (int mt = 0; mt < 4; mt++) {
        const int r0 = bm + wm * 64 + mt * 16 + g;
        #pragma unroll
        for (int nt = 0; nt < 4; nt++) {
            const int cn = h * HD + wn * 32 + nt * 8 + tig * 2;
            *(float2*)(O + (size_t)r0 * DIM + cn)       = make_float2(c[mt][nt][0], c[mt][nt][1]);
            *(float2*)(O + (size_t)(r0 + 8) * DIM + cn) = make_float2(c[mt][nt][2], c[mt][nt][3]);
        }
    }
}

// ---------------- RMS-norm + RoPE on Q and K (warp per (token, head)) ---------
__global__ __launch_bounds__(256) void norm_rope_kernel(
    float* __restrict__ Q, float* __restrict__ K,
    const float* __restrict__ csn, const float* __restrict__ snn,
    const float* __restrict__ g_q, const float* __restrict__ g_aq,
    const float* __restrict__ g_k, const float* __restrict__ g_ak)
{
    const int warp = (blockIdx.x * blockDim.x + threadIdx.x) >> 5;
    const int lane = threadIdx.x & 31;
    if (warp >= S_TOT * NHEADS) return;
    const int s = warp / NHEADS;
    const int h = warp % NHEADS;

    float* X;
    const float* g;
    if (blockIdx.y == 0) { X = Q; g = (s < S_TXT) ? g_aq : g_q; }
    else                 { X = K; g = (s < S_TXT) ? g_ak : g_k; }

    float* row = X + (size_t)s * DIM + h * HD;
    const int d = lane * 4;
    float4 x = *(float4*)(row + d);

    float ss = x.x * x.x + x.y * x.y + x.z * x.z + x.w * x.w;
    #pragma unroll
    for (int o = 16; o; o >>= 1) ss += __shfl_xor_sync(0xffffffffu, ss, o);
    const float r = rsqrtf(ss * (1.f / (float)HD) + 1e-6f);

    float4 gv = *(const float4*)(g + d);
    x.x *= r * gv.x; x.y *= r * gv.y; x.z *= r * gv.z; x.w *= r * gv.w;

    float4 cc = *(const float4*)(csn + (size_t)s * HD + d);
    float4 sn = *(const float4*)(snn + (size_t)s * HD + d);
    float4 o;
    o.x = x.x * cc.x - x.y * sn.x;
    o.y = x.y * cc.y + x.x * sn.y;
    o.z = x.z * cc.z - x.w * sn.z;
    o.w = x.w * cc.w + x.z * sn.w;
    *(float4*)(row + d) = o;
}

// ---------------- launch ------------------------------------------------------
extern "C" void kernel_launch(void* const* d_in, const int* in_sizes, int n_in,
                              void* d_out, int out_size)
{
    const float** in = (const float**)d_in;
    const float *hid = in[0], *enc = in[1], *cosr = in[2], *sinr = in[3];
    const float *Wq, *bq, *Wk, *bk, *Wv, *bv, *Waq, *baq, *Wak, *bak, *Wav, *bav;
    const float *gq, *gk, *gaq, *gak, *Wout, *bout, *Wadd, *badd;

    if (in_sizes[5] == DIM) {
        // reference-signature order
        Wq = in[4];  bq = in[5];  Wk = in[6];  bk = in[7];  Wv = in[8];  bv = in[9];
        Waq = in[10]; baq = in[11]; Wak = in[12]; bak = in[13]; Wav = in[14]; bav = in[15];
        gq = in[16]; gk = in[17]; gaq = in[18]; gak = in[19];
        Wout = in[20]; bout = in[21]; Wadd = in[22]; badd = in[23];
    } else {
        // setup_inputs dict order
        Wq = in[4]; Wk = in[5]; Wv = in[6]; Waq = in[7]; Wak = in[8]; Wav = in[9];
        Wout = in[10]; Wadd = in[11];
        bq = in[12]; bk = in[13]; bv = in[14]; baq = in[15]; bak = in[16]; bav = in[17];
        bout = in[18]; badd = in[19];
        gq = in[20]; gk = in[21]; gaq = in[22]; gak = in[23];
    }

    float *Qb, *Kb, *Vb, *Ob, *Sb;
    cudaGetSymbolAddress((void**)&Qb, g_Q);
    cudaGetSymbolAddress((void**)&Kb, g_K);
    cudaGetSymbolAddress((void**)&Vb, g_V);
    cudaGetSymbolAddress((void**)&Ob, g_O);
    cudaGetSymbolAddress((void**)&Sb, g_S);

    float* out = (float*)d_out;
    float* img_out = out;                          // [2048, 3072]
    float* enc_out = out + (size_t)S_IMG * DIM;    // [512, 3072]

    dim3 gBig(DIM / 128, S_TOT / 128);             // (24, 20)

    // 1-3. QKV projections (txt rows use Wa*, img rows use W*)
    gemm_big_mma<<<gBig, 256>>>(enc, hid, Waq, Wq, baq, bq, Qb, Qb + (size_t)S_TXT * DIM);
    gemm_big_mma<<<gBig, 256>>>(enc, hid, Wak, Wk, bak, bk, Kb, Kb + (size_t)S_TXT * DIM);
    gemm_big_mma<<<gBig, 256>>>(enc, hid, Wav, Wv, bav, bv, Vb, Vb + (size_t)S_TXT * DIM);

    // 4. RMS-norm + RoPE on Q and K (fp32)
    dim3 gNR((S_TOT * NHEADS * 32) / 256, 2);      // (7680, 2)
    norm_rope_kernel<<<gNR, 256>>>(Qb, Kb, cosr, sinr, gq, gaq, gk, gak);

    // 5. Scores S = Q K^T per head (tf32 MMA)
    dim3 gSc(S_TOT / 128, S_TOT / 128, NHEADS);    // (20, 20, 24)
    gemm_scores_mma<<<gSc, 256>>>(Qb, Kb, Sb);

    // 6. Softmax (scale folded in)
    softmax_kernel<<<NHEADS * S_TOT, 128>>>(Sb);

    // 7. O = P V per head (tf32 MMA)
    dim3 gPV(S_TOT / 128, NHEADS);                 // (20, 24)
    gemm_pv_mma<<<gPV, 256>>>(Sb, Vb, Ob);

    // 8. Output projections: txt rows -> Wadd -> enc_out; img rows -> Wout -> img_out
    gemm_big_mma<<<gBig, 256>>>(Ob, Ob + (size_t)S_TXT * DIM, Wadd, Wout, badd, bout,
                                enc_out, img_out);
}

// round 17
// speedup vs baseline: 3.4453x; 1.6050x over previous
#include <cuda_runtime.h>
#include <cuda_fp16.h>
#include <math.h>
#include <stdint.h>

#define DIM      3072
#define NHEADS   24
#define HD       128
#define S_TXT    512
#define S_IMG    2048
#define S_TOT    2560
#define SOFTMAX_SCALE 0.08838834764831845f

#define SZ_XD    (S_TOT * DIM)
#define SZ_WD    (DIM * DIM)
#define SZ_S     ((size_t)NHEADS * S_TOT * S_TOT)

#define PADU 20   // uint32 (=fp16-pair) pitch per 128-row tile; conflict-free frags

// ---------------- scratch -----------------------------------------------------
__device__ float g_Q[SZ_XD];
__device__ float g_K[SZ_XD];
__device__ float g_V[SZ_XD];
__device__ float g_O[SZ_XD];
__device__ float g_S[SZ_S];
__device__ __half g_Xh[SZ_XD];
__device__ __half g_Wt[8][SZ_WD];     // weights transposed: [n][k] fp16
__device__ __half g_Qh[SZ_XD], g_Kh[SZ_XD];
__device__ __half g_Vth[SZ_XD];       // V transposed per head: [24][128][2560]
__device__ __half g_Ph[SZ_S];
__device__ __half g_Oh[SZ_XD];

// ---------------- helpers ------------------------------------------------------
__device__ __forceinline__ uint32_t f2h2(float x, float y) {
    __half2 h = __floats2half2_rn(x, y);
    return *reinterpret_cast<uint32_t*>(&h);
}

__device__ __forceinline__ void mma_fp16(float c[4],
    uint32_t a0, uint32_t a1, uint32_t a2, uint32_t a3,
    uint32_t b0, uint32_t b1)
{
    asm volatile(
        "mma.sync.aligned.m16n8k16.row.col.f32.f16.f16.f32 "
        "{%0,%1,%2,%3},{%4,%5,%6,%7},{%8,%9},{%0,%1,%2,%3};"
        : "+f"(c[0]), "+f"(c[1]), "+f"(c[2]), "+f"(c[3])
        : "r"(a0), "r"(a1), "r"(a2), "r"(a3), "r"(b0), "r"(b1));
}

// ---------------- fp16 NT GEMM core: C[128,128] = A·B^T (+bias) ----------------
// A: [*, lda] fp16 row-major (k contiguous); B: [*, ldb] fp16 row-major.
// BK = 32 halves per stage; 256 thr, 8 warps 2(M)x4(N), warp tile 64x32,
// m16n8k16, register prefetch double-buffering.
__device__ __forceinline__ void gemm_nt(
    const __half* __restrict__ A, int lda,
    const __half* __restrict__ B, int ldb,
    int ktiles, float* __restrict__ C, int ldc, const float* __restrict__ bias)
{
    __shared__ uint32_t As[128][PADU];
    __shared__ uint32_t Bs[128][PADU];

    const int tid  = threadIdx.x;
    const int warp = tid >> 5, lane = tid & 31;
    const int g = lane >> 2, tig = lane & 3;
    const int wm = warp >> 2, wn = warp & 3;

    const int arow  = tid >> 1;          // 0..127
    const int ah0   = (tid & 1) * 16;    // half-index base within BK=32
    const int apair = (tid & 1) * 8;     // pair-index base

    const __half* Ap = A + (size_t)arow * lda + ah0;
    const __half* Bp = B + (size_t)arow * ldb + ah0;

    float c[4][4][4];
    #pragma unroll
    for (int mt = 0; mt < 4; mt++)
        #pragma unroll
        for (int nt = 0; nt < 4; nt++)
            #pragma unroll
            for (int i = 0; i < 4; i++) c[mt][nt][i] = 0.f;

    uint4 ua0 = *(const uint4*)(Ap);
    uint4 ua1 = *(const uint4*)(Ap + 8);
    uint4 ub0 = *(const uint4*)(Bp);
    uint4 ub1 = *(const uint4*)(Bp + 8);

    for (int t = 0; t < ktiles; ++t) {
        *(uint4*)&As[arow][apair]     = ua0;
        *(uint4*)&As[arow][apair + 4] = ua1;
        *(uint4*)&Bs[arow][apair]     = ub0;
        *(uint4*)&Bs[arow][apair + 4] = ub1;
        __syncthreads();

        if (t + 1 < ktiles) {
            const int k0 = (t + 1) * 32;
            ua0 = *(const uint4*)(Ap + k0);
            ua1 = *(const uint4*)(Ap + k0 + 8);
            ub0 = *(const uint4*)(Bp + k0);
            ub1 = *(const uint4*)(Bp + k0 + 8);
        }

        #pragma unroll
        for (int ks = 0; ks < 2; ++ks) {
            uint32_t af[4][4], bf[4][2];
            #pragma unroll
            for (int mt = 0; mt < 4; mt++) {
                const int r0 = wm * 64 + mt * 16 + g;
                af[mt][0] = As[r0][ks * 8 + tig];
                af[mt][1] = As[r0 + 8][ks * 8 + tig];
                af[mt][2] = As[r0][ks * 8 + tig + 4];
                af[mt][3] = As[r0 + 8][ks * 8 + tig + 4];
            }
            #pragma unroll
            for (int nt = 0; nt < 4; nt++) {
                const int rn = wn * 32 + nt * 8 + g;
                bf[nt][0] = Bs[rn][ks * 8 + tig];
                bf[nt][1] = Bs[rn][ks * 8 + tig + 4];
            }
            #pragma unroll
            for (int mt = 0; mt < 4; mt++)
                #pragma unroll
                for (int nt = 0; nt < 4; nt++)
                    mma_fp16(c[mt][nt], af[mt][0], af[mt][1], af[mt][2], af[mt][3],
                             bf[nt][0], bf[nt][1]);
        }
        __syncthreads();
    }

    #pragma unroll
    for (int mt = 0; mt < 4; mt++) {
        const int r0 = wm * 64 + mt * 16 + g;
        #pragma unroll
        for (int nt = 0; nt < 4; nt++) {
            const int cn = wn * 32 + nt * 8 + tig * 2;
            float bx = 0.f, by = 0.f;
            if (bias) { bx = bias[cn]; by = bias[cn + 1]; }
            *(float2*)(C + (size_t)r0 * ldc + cn) =
                make_float2(c[mt][nt][0] + bx, c[mt][nt][1] + by);
            *(float2*)(C + (size_t)(r0 + 8) * ldc + cn) =
                make_float2(c[mt][nt][2] + bx, c[mt][nt][3] + by);
        }
    }
}

// ---------------- GEMM wrappers ------------------------------------------------
__global__ __launch_bounds__(256) void k_proj(
    const __half* __restrict__ Xh,
    const __half* __restrict__ W0t, const __half* __restrict__ W1t,
    const float* __restrict__ b0, const float* __restrict__ b1,
    float* __restrict__ C)
{
    const int bn = blockIdx.x * 128, bm = blockIdx.y * 128;
    const __half* Bt; const float* bias;
    if (bm < S_TXT) { Bt = W0t; bias = b0; }
    else            { Bt = W1t; bias = b1; }
    gemm_nt(Xh + (size_t)bm * DIM, DIM, Bt + (size_t)bn * DIM, DIM,
            DIM / 32, C + (size_t)bm * DIM + bn, DIM, bias + bn);
}

__global__ __launch_bounds__(256) void k_outproj(
    const __half* __restrict__ Oh,
    const __half* __restrict__ W0t, const __half* __restrict__ W1t,
    const float* __restrict__ b0, const float* __restrict__ b1,
    float* __restrict__ enc_out, float* __restrict__ img_out)
{
    const int bn = blockIdx.x * 128, bm = blockIdx.y * 128;
    const __half* Bt; const float* bias; float* Cp;
    if (bm < S_TXT) { Bt = W0t; bias = b0; Cp = enc_out + (size_t)bm * DIM; }
    else            { Bt = W1t; bias = b1; Cp = img_out + (size_t)(bm - S_TXT) * DIM; }
    gemm_nt(Oh + (size_t)bm * DIM, DIM, Bt + (size_t)bn * DIM, DIM,
            DIM / 32, Cp + bn, DIM, bias + bn);
}

__global__ __launch_bounds__(256) void k_scores(
    const __half* __restrict__ Qh, const __half* __restrict__ Kh,
    float* __restrict__ S)
{
    const int h = blockIdx.z, bm = blockIdx.y * 128, bn = blockIdx.x * 128;
    gemm_nt(Qh + (size_t)bm * DIM + h * HD, DIM,
            Kh + (size_t)bn * DIM + h * HD, DIM,
            HD / 32,
            S + (size_t)h * S_TOT * S_TOT + (size_t)bm * S_TOT + bn, S_TOT, nullptr);
}

__global__ __launch_bounds__(256) void k_pv(
    const __half* __restrict__ Ph, const __half* __restrict__ Vth,
    float* __restrict__ O)
{
    const int h = blockIdx.y, bm = blockIdx.x * 128;
    gemm_nt(Ph + (size_t)h * S_TOT * S_TOT + (size_t)bm * S_TOT, S_TOT,
            Vth + (size_t)h * HD * S_TOT, S_TOT,
            S_TOT / 32, O + (size_t)bm * DIM + h * HD, DIM, nullptr);
}

// ---------------- conversion kernels -------------------------------------------
__global__ __launch_bounds__(256) void build_X_h(
    const float4* __restrict__ enc, const float4* __restrict__ hid,
    uint2* __restrict__ dst)
{
    const int i = blockIdx.x * blockDim.x + threadIdx.x;
    if (i >= SZ_XD / 4) return;
    const int row = i / (DIM / 4);
    float4 v = (row < S_TXT) ? enc[i] : hid[i - S_TXT * (DIM / 4)];
    dst[i] = make_uint2(f2h2(v.x, v.y), f2h2(v.z, v.w));
}

__global__ __launch_bounds__(256) void convert_rows_h(
    const float4* __restrict__ src, uint2* __restrict__ dst, int n4)
{
    const int i = blockIdx.x * blockDim.x + threadIdx.x;
    if (i >= n4) return;
    float4 v = src[i];
    dst[i] = make_uint2(f2h2(v.x, v.y), f2h2(v.z, v.w));
}

// dst[z][c][r] = fp16(src[r][z*C + c]); 32x32 tiles, 256 threads.
__global__ __launch_bounds__(256) void transpose_h(
    const float* __restrict__ src, int lds, int R, int C,
    __half* __restrict__ dst)
{
    __shared__ float t[32][33];
    const int z = blockIdx.z;
    const int c0 = blockIdx.x * 32, r0 = blockIdx.y * 32;
    const int tx = threadIdx.x & 31, ty = threadIdx.x >> 5;
    const float* s = src + (size_t)z * C;
    #pragma unroll
    for (int j = 0; j < 4; j++)
        t[ty + j * 8][tx] = s[(size_t)(r0 + ty + j * 8) * lds + c0 + tx];
    __syncthreads();
    __half* o = dst + (size_t)z * C * R;
    #pragma unroll
    for (int j = 0; j < 4; j++) {
        const int cc = ty + j * 8;
        o[(size_t)(c0 + cc) * R + r0 + tx] = __float2half_rn(t[tx][cc]);
    }
}

// ---------------- RMS-norm + RoPE -> fp16 --------------------------------------
__global__ __launch_bounds__(256) void norm_rope_h(
    const float* __restrict__ Qf, const float* __restrict__ Kf,
    __half* __restrict__ Qh, __half* __restrict__ Kh,
    const float* __restrict__ csn, const float* __restrict__ snn,
    const float* __restrict__ g_q, const float* __restrict__ g_aq,
    const float* __restrict__ g_k, const float* __restrict__ g_ak)
{
    const int warp = (blockIdx.x * blockDim.x + threadIdx.x) >> 5;
    const int lane = threadIdx.x & 31;
    if (warp >= S_TOT * NHEADS) return;
    const int s = warp / NHEADS;
    const int h = warp % NHEADS;

    const float* X; __half* D; const float* g;
    if (blockIdx.y == 0) { X = Qf; D = Qh; g = (s < S_TXT) ? g_aq : g_q; }
    else                 { X = Kf; D = Kh; g = (s < S_TXT) ? g_ak : g_k; }

    const size_t rowoff = (size_t)s * DIM + h * HD;
    const int d = lane * 4;
    float4 x = *(const float4*)(X + rowoff + d);

    float ss = x.x * x.x + x.y * x.y + x.z * x.z + x.w * x.w;
    #pragma unroll
    for (int o = 16; o; o >>= 1) ss += __shfl_xor_sync(0xffffffffu, ss, o);
    const float r = rsqrtf(ss * (1.f / (float)HD) + 1e-6f);

    float4 gv = *(const float4*)(g + d);
    x.x *= r * gv.x; x.y *= r * gv.y; x.z *= r * gv.z; x.w *= r * gv.w;

    float4 cc = *(const float4*)(csn + (size_t)s * HD + d);
    float4 sn = *(const float4*)(snn + (size_t)s * HD + d);
    float4 o;
    o.x = x.x * cc.x - x.y * sn.x;
    o.y = x.y * cc.y + x.x * sn.y;
    o.z = x.z * cc.z - x.w * sn.z;
    o.w = x.w * cc.w + x.z * sn.w;

    *(uint2*)(D + rowoff + d) = make_uint2(f2h2(o.x, o.y), f2h2(o.z, o.w));
}

// ---------------- softmax: fp32 row -> fp16 probs -------------------------------
__global__ __launch_bounds__(128) void softmax_h(
    const float* __restrict__ S, __half* __restrict__ P)
{
    const float4* row = (const float4*)(S + (size_t)blockIdx.x * S_TOT);
    uint2* pr = (uint2*)(P + (size_t)blockIdx.x * S_TOT);
    const int tid = threadIdx.x;
    __shared__ float red[4];

    float4 v[5];
    float m = -1e30f;
    #pragma unroll
    for (int i = 0; i < 5; i++) {
        v[i] = row[tid + i * 128];
        m = fmaxf(m, fmaxf(fmaxf(v[i].x, v[i].y), fmaxf(v[i].z, v[i].w)));
    }
    #pragma unroll
    for (int o = 16; o; o >>= 1) m = fmaxf(m, __shfl_xor_sync(0xffffffffu, m, o));
    const int wid = tid >> 5, lane = tid & 31;
    if (lane == 0) red[wid] = m;
    __syncthreads();
    const float mm = fmaxf(fmaxf(red[0], red[1]), fmaxf(red[2], red[3]));
    __syncthreads();

    float sum = 0.f;
    #pragma unroll
    for (int i = 0; i < 5; i++) {
        v[i].x = __expf((v[i].x - mm) * SOFTMAX_SCALE);
        v[i].y = __expf((v[i].y - mm) * SOFTMAX_SCALE);
        v[i].z = __expf((v[i].z - mm) * SOFTMAX_SCALE);
        v[i].w = __expf((v[i].w - mm) * SOFTMAX_SCALE);
        sum += v[i].x + v[i].y + v[i].z + v[i].w;
    }
    #pragma unroll
    for (int o = 16; o; o >>= 1) sum += __shfl_xor_sync(0xffffffffu, sum, o);
    if (lane == 0) red[wid] = sum;
    __syncthreads();
    const float inv = 1.f / (red[0] + red[1] + red[2] + red[3]);
    #pragma unroll
    for (int i = 0; i < 5; i++)
        pr[tid + i * 128] = make_uint2(f2h2(v[i].x * inv, v[i].y * inv),
                                       f2h2(v[i].z * inv, v[i].w * inv));
}

// ---------------- launch ------------------------------------------------------
extern "C" void kernel_launch(void* const* d_in, const int* in_sizes, int n_in,
                              void* d_out, int out_size)
{
    const float** in = (const float**)d_in;
    const float *hid = in[0], *enc = in[1], *cosr = in[2], *sinr = in[3];
    const float *Wq, *bq, *Wk, *bk, *Wv, *bv, *Waq, *baq, *Wak, *bak, *Wav, *bav;
    const float *gq, *gk, *gaq, *gak, *Wout, *bout, *Wadd, *badd;

    if (in_sizes[5] == DIM) {
        Wq = in[4];  bq = in[5];  Wk = in[6];  bk = in[7];  Wv = in[8];  bv = in[9];
        Waq = in[10]; baq = in[11]; Wak = in[12]; bak = in[13]; Wav = in[14]; bav = in[15];
        gq = in[16]; gk = in[17]; gaq = in[18]; gak = in[19];
        Wout = in[20]; bout = in[21]; Wadd = in[22]; badd = in[23];
    } else {
        Wq = in[4]; Wk = in[5]; Wv = in[6]; Waq = in[7]; Wak = in[8]; Wav = in[9];
        Wout = in[10]; Wadd = in[11];
        bq = in[12]; bk = in[13]; bv = in[14]; baq = in[15]; bak = in[16]; bav = in[17];
        bout = in[18]; badd = in[19];
        gq = in[20]; gk = in[21]; gaq = in[22]; gak = in[23];
    }

    float *Qb, *Kb, *Vb, *Ob, *Sb;
    __half *Xh, *Wt, *Qh, *Kh, *VTh, *Ph, *Oh;
    cudaGetSymbolAddress((void**)&Qb, g_Q);
    cudaGetSymbolAddress((void**)&Kb, g_K);
    cudaGetSymbolAddress((void**)&Vb, g_V);
    cudaGetSymbolAddress((void**)&Ob, g_O);
    cudaGetSymbolAddress((void**)&Sb, g_S);
    cudaGetSymbolAddress((void**)&Xh, g_Xh);
    cudaGetSymbolAddress((void**)&Wt, g_Wt);
    cudaGetSymbolAddress((void**)&Qh, g_Qh);
    cudaGetSymbolAddress((void**)&Kh, g_Kh);
    cudaGetSymbolAddress((void**)&VTh, g_Vth);
    cudaGetSymbolAddress((void**)&Ph, g_Ph);
    cudaGetSymbolAddress((void**)&Oh, g_Oh);

    float* out = (float*)d_out;
    float* img_out = out;
    float* enc_out = out + (size_t)S_IMG * DIM;

    // 0. inputs -> fp16; weights transposed [n][k] fp16
    build_X_h<<<SZ_XD / 4 / 256, 256>>>((const float4*)enc, (const float4*)hid, (uint2*)Xh);
    const float* Ws[8] = {Waq, Wq, Wak, Wk, Wav, Wv, Wadd, Wout};
    dim3 gT(DIM / 32, DIM / 32, 1);
    for (int i = 0; i < 8; i++)
        transpose_h<<<gT, 256>>>(Ws[i], DIM, DIM, DIM, Wt + (size_t)i * SZ_WD);

    // 1-3. QKV projections (fp16 NT)
    dim3 gBig(DIM / 128, S_TOT / 128);
    k_proj<<<gBig, 256>>>(Xh, Wt + 0 * (size_t)SZ_WD, Wt + 1 * (size_t)SZ_WD, baq, bq, Qb);
    k_proj<<<gBig, 256>>>(Xh, Wt + 2 * (size_t)SZ_WD, Wt + 3 * (size_t)SZ_WD, bak, bk, Kb);
    k_proj<<<gBig, 256>>>(Xh, Wt + 4 * (size_t)SZ_WD, Wt + 5 * (size_t)SZ_WD, bav, bv, Vb);

    // 4. RMS-norm + RoPE -> fp16
    dim3 gNR((S_TOT * NHEADS * 32) / 256, 2);
    norm_rope_h<<<gNR, 256>>>(Qb, Kb, Qh, Kh, cosr, sinr, gq, gaq, gk, gak);

    // 5. V transpose per head -> fp16 [24][128][2560]
    dim3 gVT(HD / 32, S_TOT / 32, NHEADS);
    transpose_h<<<gVT, 256>>>(Vb, DIM, S_TOT, HD, VTh);

    // 6. scores (fp16 NT)
    dim3 gSc(S_TOT / 128, S_TOT / 128, NHEADS);
    k_scores<<<gSc, 256>>>(Qh, Kh, Sb);

    // 7. softmax -> fp16 probs
    softmax_h<<<NHEADS * S_TOT, 128>>>(Sb, Ph);

    // 8. O = P V (fp16 NT)
    dim3 gPV(S_TOT / 128, NHEADS);
    k_pv<<<gPV, 256>>>(Ph, VTh, Ob);

    // 9. O -> fp16; output projections (fp16 NT)
    convert_rows_h<<<SZ_XD / 4 / 256, 256>>>((const float4*)Ob, (uint2*)Oh, SZ_XD / 4);
    k_outproj<<<gBig, 256>>>(Oh, Wt + 6 * (size_t)SZ_WD, Wt + 7 * (size_t)SZ_WD,
                             badd, bout, enc_out, img_out);
}